// round 17
// baseline (speedup 1.0000x reference)
#include <cuda_runtime.h>
#include <cuda_bf16.h>
#include <cuda_fp16.h>
#include <math.h>
#include <stdint.h>

// Problem constants
#define NHEADS 6
#define HS     24
#define NE     144      // N_EMBD
#define TT     128
#define MAXB   256
#define MTOT   (MAXB * TT)   // 32768

// Pre-split bf16 images (allocation-free __device__ globals)
__device__ __align__(16) __nv_bfloat16 g_xh[MTOT * NE];
__device__ __align__(16) __nv_bfloat16 g_xl[MTOT * NE];
__device__ __align__(16) __nv_bfloat16 g_qh[MTOT * NE];
__device__ __align__(16) __nv_bfloat16 g_ql[MTOT * NE];
__device__ __align__(16) __nv_bfloat16 g_kh[MTOT * NE];
__device__ __align__(16) __nv_bfloat16 g_kl[MTOT * NE];
__device__ __align__(16) __nv_bfloat16 g_vh[MTOT * NE];
__device__ __align__(16) __nv_bfloat16 g_vl[MTOT * NE];
__device__ __align__(16) __nv_bfloat16 g_ctxh[MTOT * NE];
__device__ __align__(16) __nv_bfloat16 g_ctxl[MTOT * NE];
__device__ __align__(16) __nv_bfloat16 g_relh[TT * HS];   // rel rows 127..254, hi

// Weight images: 4 weights x [hi|lo] x [n=144][k padded to 152] bf16
#define WROW 152
#define WIMG_SPLIT (NE * WROW)
#define WIMG_PER_W (2 * WIMG_SPLIT)
__device__ __align__(16) __nv_bfloat16 g_wimg[4 * WIMG_PER_W];

// ===========================================================================
// PTX helpers (baseline PTX only)
// ===========================================================================
__device__ __forceinline__ uint32_t s2u(const void* p) {
    uint32_t a;
    asm("{ .reg .u64 t; cvta.to.shared.u64 t, %1; cvt.u32.u64 %0, t; }"
        : "=r"(a) : "l"(p));
    return a;
}
#define LDSM4(r0, r1, r2, r3, addr)                                          \
    asm volatile("ldmatrix.sync.aligned.m8n8.x4.shared.b16 {%0,%1,%2,%3}, [%4];" \
                 : "=r"(r0), "=r"(r1), "=r"(r2), "=r"(r3) : "r"(addr))
#define LDSM2(r0, r1, addr)                                                  \
    asm volatile("ldmatrix.sync.aligned.m8n8.x2.shared.b16 {%0,%1}, [%2];"   \
                 : "=r"(r0), "=r"(r1) : "r"(addr))
#define LDSM4T(r0, r1, r2, r3, addr)                                         \
    asm volatile("ldmatrix.sync.aligned.m8n8.x4.trans.shared.b16 {%0,%1,%2,%3}, [%4];" \
                 : "=r"(r0), "=r"(r1), "=r"(r2), "=r"(r3) : "r"(addr))
#define LDSM2T(r0, r1, addr)                                                 \
    asm volatile("ldmatrix.sync.aligned.m8n8.x2.trans.shared.b16 {%0,%1}, [%2];" \
                 : "=r"(r0), "=r"(r1) : "r"(addr))
#define MMA16816(acc, a0, a1, a2, a3, b0, b1)                                \
    asm volatile("mma.sync.aligned.m16n8k16.row.col.f32.bf16.bf16.f32 "      \
                 "{%0,%1,%2,%3}, {%4,%5,%6,%7}, {%8,%9}, {%0,%1,%2,%3};"     \
                 : "+f"((acc)[0]), "+f"((acc)[1]), "+f"((acc)[2]), "+f"((acc)[3]) \
                 : "r"(a0), "r"(a1), "r"(a2), "r"(a3), "r"(b0), "r"(b1))

__device__ __forceinline__ void bsplit(float x, float y, uint32_t& hi, uint32_t& lo) {
    __nv_bfloat16 hx = __float2bfloat16(x), hy = __float2bfloat16(y);
    __nv_bfloat162 H = __halves2bfloat162(hx, hy);
    __nv_bfloat162 L = __halves2bfloat162(__float2bfloat16(x - __bfloat162float(hx)),
                                          __float2bfloat16(y - __bfloat162float(hy)));
    hi = *(uint32_t*)&H;
    lo = *(uint32_t*)&L;
}

// ===========================================================================
// Prep kernels
// ===========================================================================
__global__ void __launch_bounds__(256) prep_w(const float* __restrict__ Wq,
                                              const float* __restrict__ Wk,
                                              const float* __restrict__ Wv,
                                              const float* __restrict__ Wp) {
    const float* W = (blockIdx.x == 0) ? Wq : (blockIdx.x == 1) ? Wk
                   : (blockIdx.x == 2) ? Wv : Wp;
    __nv_bfloat16* dst = g_wimg + blockIdx.x * WIMG_PER_W;
    for (int idx = threadIdx.x; idx < NE * NE; idx += 256) {
        int k = idx / NE, n = idx - k * NE;
        float v = W[idx];
        __nv_bfloat16 h = __float2bfloat16(v);
        __nv_bfloat16 l = __float2bfloat16(v - __bfloat162float(h));
        dst[n * WROW + k] = h;
        dst[WIMG_SPLIT + n * WROW + k] = l;
    }
}

// x -> bf16 hi/lo images (row-major [m][144], streaming)
__global__ void __launch_bounds__(256) prep_a(const float* __restrict__ x) {
    int idx4 = blockIdx.x * 256 + threadIdx.x;      // 1,179,648 float4 total
    float4 f = ((const float4*)x)[idx4];
    uint32_t h0, l0, h1, l1;
    bsplit(f.x, f.y, h0, l0);
    bsplit(f.z, f.w, h1, l1);
    ((uint2*)g_xh)[idx4] = make_uint2(h0, h1);
    ((uint2*)g_xl)[idx4] = make_uint2(l0, l1);
}

// rel rows 127..254 -> bf16 hi image [128][24]
__global__ void __launch_bounds__(256) prep_rel(const float* __restrict__ rel) {
    for (int idx = threadIdx.x; idx < TT * HS; idx += 256)
        g_relh[idx] = __float2bfloat16(rel[(size_t)127 * HS + idx]);
}

// ===========================================================================
// Tensor-core GEMM v4: k-outer, A direct from pre-split bf16 global images.
// Epilogue: fp32+bias (proj, Cf!=null) OR bf16 hi/lo images (qkv).
// 256 threads (8 warps: 4 row-stripes x 2 n-halves), M-tile 64.
// Smem = W image only (87552 B) -> 2 CTAs/SM.
// ===========================================================================
#define WLOFF 43776
#define GEMM_SMEM 87552

__device__ __forceinline__ void gemm_mma_body(const __nv_bfloat16* __restrict__ Ah,
                                              const __nv_bfloat16* __restrict__ Al,
                                              const __nv_bfloat16* __restrict__ wimg,
                                              const float* __restrict__ bias,
                                              float* __restrict__ Cf,
                                              __nv_bfloat16* __restrict__ Chi,
                                              __nv_bfloat16* __restrict__ Clo) {
    extern __shared__ char sm[];
    const uint32_t su = s2u(sm);
    const int tid = threadIdx.x;
    const int lane = tid & 31;
    const int wid = tid >> 5;
    const int bm = blockIdx.x * 64;

    // W image copy (hi+lo, 87552 B)
    {
        const float4* src = (const float4*)wimg;
        float4* dst = (float4*)sm;
        for (int i = tid; i < 5472; i += 256) dst[i] = src[i];
    }
    __syncthreads();

    const int r0 = (wid >> 1) * 16;
    const int nbase = (wid & 1) * 72;
    const int row = bm + r0 + (lane >> 2);
    const __nv_bfloat16* Ah_r  = Ah + (size_t)row * NE;
    const __nv_bfloat16* Ah_r8 = Ah_r + 8 * NE;
    const __nv_bfloat16* Al_r  = Al + (size_t)row * NE;
    const __nv_bfloat16* Al_r8 = Al_r + 8 * NE;
    const int kc = (lane & 3) * 2;

    const uint32_t boff =
        (uint32_t)((nbase + (lane & 7) + ((lane >> 4) & 1) * 8) * WROW) * 2
        + ((lane >> 3) & 1) * 16;
    const uint32_t b2off =
        (uint32_t)((nbase + 64 + (lane & 7)) * WROW) * 2
        + ((lane >> 3) & 1) * 16;

    float acc[9][4];
#pragma unroll
    for (int nt = 0; nt < 9; nt++)
#pragma unroll
        for (int i = 0; i < 4; i++) acc[nt][i] = 0.f;

#pragma unroll
    for (int s = 0; s < 9; s++) {
        const int k0 = s * 16;
        uint32_t ah0 = *(const uint32_t*)(Ah_r  + k0 + kc);
        uint32_t ah1 = *(const uint32_t*)(Ah_r8 + k0 + kc);
        uint32_t ah2 = *(const uint32_t*)(Ah_r  + k0 + 8 + kc);
        uint32_t ah3 = *(const uint32_t*)(Ah_r8 + k0 + 8 + kc);
        uint32_t al0 = *(const uint32_t*)(Al_r  + k0 + kc);
        uint32_t al1 = *(const uint32_t*)(Al_r8 + k0 + kc);
        uint32_t al2 = *(const uint32_t*)(Al_r  + k0 + 8 + kc);
        uint32_t al3 = *(const uint32_t*)(Al_r8 + k0 + 8 + kc);

#pragma unroll
        for (int np = 0; np < 4; np++) {
            const uint32_t wo = boff + np * (16 * WROW * 2) + s * 32;
            uint32_t bh0, bh1, bh2, bh3, bl0, bl1, bl2, bl3;
            LDSM4(bh0, bh1, bh2, bh3, su + wo);
            LDSM4(bl0, bl1, bl2, bl3, su + WLOFF + wo);
            MMA16816(acc[2 * np],     ah0, ah1, ah2, ah3, bh0, bh1);
            MMA16816(acc[2 * np],     al0, al1, al2, al3, bh0, bh1);
            MMA16816(acc[2 * np],     ah0, ah1, ah2, ah3, bl0, bl1);
            MMA16816(acc[2 * np + 1], ah0, ah1, ah2, ah3, bh2, bh3);
            MMA16816(acc[2 * np + 1], al0, al1, al2, al3, bh2, bh3);
            MMA16816(acc[2 * np + 1], ah0, ah1, ah2, ah3, bl2, bl3);
        }
        {
            uint32_t ch0, ch1, cl0, cl1;
            LDSM2(ch0, ch1, su + b2off + s * 32);
            LDSM2(cl0, cl1, su + WLOFF + b2off + s * 32);
            MMA16816(acc[8], ah0, ah1, ah2, ah3, ch0, ch1);
            MMA16816(acc[8], al0, al1, al2, al3, ch0, ch1);
            MMA16816(acc[8], ah0, ah1, ah2, ah3, cl0, cl1);
        }
    }

    const int g = lane >> 2, tg = lane & 3;
    const size_t m0 = (size_t)(bm + r0 + g) * NE;
    const size_t m1 = (size_t)(bm + r0 + g + 8) * NE;
    if (Cf) {
#pragma unroll
        for (int nt = 0; nt < 9; nt++) {
            int col = nbase + nt * 8 + tg * 2;
            float b0 = bias[col], b1 = bias[col + 1];
            *(float2*)(Cf + m0 + col) = make_float2(acc[nt][0] + b0, acc[nt][1] + b1);
            *(float2*)(Cf + m1 + col) = make_float2(acc[nt][2] + b0, acc[nt][3] + b1);
        }
    } else {
#pragma unroll
        for (int nt = 0; nt < 9; nt++) {
            int col = nbase + nt * 8 + tg * 2;
            uint32_t hh, ll;
            bsplit(acc[nt][0], acc[nt][1], hh, ll);
            *(uint32_t*)(Chi + m0 + col) = hh;
            *(uint32_t*)(Clo + m0 + col) = ll;
            bsplit(acc[nt][2], acc[nt][3], hh, ll);
            *(uint32_t*)(Chi + m1 + col) = hh;
            *(uint32_t*)(Clo + m1 + col) = ll;
        }
    }
}

__global__ void __launch_bounds__(256, 2) gemm_qkv_mma() {
    __nv_bfloat16* Chi = (blockIdx.y == 0) ? g_qh : (blockIdx.y == 1) ? g_kh : g_vh;
    __nv_bfloat16* Clo = (blockIdx.y == 0) ? g_ql : (blockIdx.y == 1) ? g_kl : g_vl;
    gemm_mma_body(g_xh, g_xl, g_wimg + blockIdx.y * WIMG_PER_W,
                  nullptr, nullptr, Chi, Clo);
}
__global__ void __launch_bounds__(256, 2) gemm_proj_mma(const float* __restrict__ bp,
                                                        float* __restrict__ out) {
    gemm_mma_body(g_ctxh, g_ctxl, g_wimg + 3 * WIMG_PER_W, bp, out, nullptr, nullptr);
}

// ===========================================================================
// Tensorized attention v4: prologue is a pure bf16 copy (no conversion).
// ===========================================================================
#define AQH 0
#define AQL 10240
#define AKH 20480
#define AKL 30720
#define ARH 40960
#define AVH 51200
#define AVL 61440
#define ASB 71680
#define SBW 132
#define ATTN_SMEM (ASB + 128 * SBW * 2)   // 105472 B -> 2 CTAs/SM

__global__ void __launch_bounds__(256, 2) attn_kernel() {
    extern __shared__ char sm[];
    const uint32_t su = s2u(sm);
    const int h = blockIdx.x, b = blockIdx.y;
    const size_t base = (size_t)b * (TT * NE) + (size_t)h * (TT * HS);
    const int tid = threadIdx.x;
    const int lane = tid & 31, wid = tid >> 5;

    // ---- prologue: straight bf16 copies into padded smem images ----
#pragma unroll
    for (int i = 0; i < 3; i++) {
        int idx = tid + i * 256;          // 0..767
        int r = idx / 6, c4 = idx % 6;
        uint32_t o = (uint32_t)r * 80 + (uint32_t)c4 * 8;
        size_t go = base + (size_t)r * HS + c4 * 4;
        *(uint2*)(sm + AQH + o) = *(const uint2*)(g_qh + go);
        *(uint2*)(sm + AQL + o) = *(const uint2*)(g_ql + go);
        *(uint2*)(sm + AKH + o) = *(const uint2*)(g_kh + go);
        *(uint2*)(sm + AKL + o) = *(const uint2*)(g_kl + go);
        *(uint2*)(sm + AVH + o) = *(const uint2*)(g_vh + go);
        *(uint2*)(sm + AVL + o) = *(const uint2*)(g_vl + go);
        *(uint2*)(sm + ARH + o) = *(const uint2*)(g_relh + r * HS + c4 * 4);
    }
    // zero pad cols 24..31 (bytes 48..63) of all 7 images
    for (int idx = tid; idx < 896; idx += 256) {
        int img = idx >> 7, r = idx & 127;
        *(uint4*)(sm + img * 10240 + r * 80 + 48) = make_uint4(0, 0, 0, 0);
    }
    __syncthreads();

    const int r0 = wid * 16;
    const int g = lane >> 2, tg = lane & 3;
    const int t0 = r0 + g, t1 = t0 + 8;
    const uint32_t aoff =
        (uint32_t)((r0 + (lane & 7) + ((lane >> 3) & 1) * 8) * 80)
        + ((lane >> 4) & 1) * 16;
    const uint32_t boff =
        (uint32_t)(((lane & 7) + ((lane >> 4) & 1) * 8) * 80)
        + ((lane >> 3) & 1) * 16;

    __half* SB = (__half*)(sm + ASB);

    // P' GEMM: Qhi @ relhi^T
    {
        float pa[16][4];
#pragma unroll
        for (int nt = 0; nt < 16; nt++)
#pragma unroll
            for (int i = 0; i < 4; i++) pa[nt][i] = 0.f;
#pragma unroll
        for (int s = 0; s < 2; s++) {
            uint32_t a0, a1, a2, a3;
            LDSM4(a0, a1, a2, a3, su + AQH + aoff + s * 32);
#pragma unroll
            for (int np = 0; np < 8; np++) {
                uint32_t b0, b1, b2, b3;
                LDSM4(b0, b1, b2, b3, su + ARH + boff + np * 1280 + s * 32);
                MMA16816(pa[2 * np],     a0, a1, a2, a3, b0, b1);
                MMA16816(pa[2 * np + 1], a0, a1, a2, a3, b2, b3);
            }
        }
#pragma unroll
        for (int nt = 0; nt < 16; nt++) {
            int u = nt * 8 + tg * 2;
            if (u     <= t0) SB[t0 * SBW + (t0 - u)]     = __float2half_rn(pa[nt][0]);
            if (u + 1 <= t0) SB[t0 * SBW + (t0 - u - 1)] = __float2half_rn(pa[nt][1]);
            if (u     <= t1) SB[t1 * SBW + (t1 - u)]     = __float2half_rn(pa[nt][2]);
            if (u + 1 <= t1) SB[t1 * SBW + (t1 - u - 1)] = __float2half_rn(pa[nt][3]);
        }
    }
    __syncwarp();

    // S1 GEMM: Qhi.Khi + Qhi.Klo + Qlo.Khi
    float sa[16][4];
#pragma unroll
    for (int nt = 0; nt < 16; nt++)
#pragma unroll
        for (int i = 0; i < 4; i++) sa[nt][i] = 0.f;
#pragma unroll 1
    for (int p = 0; p < 3; p++) {
        const uint32_t Ai = su + ((p == 2) ? AQL : AQH) + aoff;
        const uint32_t Bi = su + ((p == 1) ? AKL : AKH) + boff;
#pragma unroll
        for (int s = 0; s < 2; s++) {
            uint32_t a0, a1, a2, a3;
            LDSM4(a0, a1, a2, a3, Ai + s * 32);
#pragma unroll
            for (int np = 0; np < 8; np++) {
                uint32_t b0, b1, b2, b3;
                LDSM4(b0, b1, b2, b3, Bi + np * 1280 + s * 32);
                MMA16816(sa[2 * np],     a0, a1, a2, a3, b0, b1);
                MMA16816(sa[2 * np + 1], a0, a1, a2, a3, b2, b3);
            }
        }
    }

    // merge + mask + softmax
    const float scale = 0.20412414523193154f;
    float m0 = -INFINITY, m1 = -INFINITY;
#pragma unroll
    for (int nt = 0; nt < 16; nt++) {
        int s = nt * 8 + tg * 2;
        __half2 q0 = *(__half2*)(SB + t0 * SBW + s);
        __half2 q1 = *(__half2*)(SB + t1 * SBW + s);
        float v;
        v = (s     <= t0) ? fmaf(scale, sa[nt][0], __low2float(q0))  : -INFINITY;
        sa[nt][0] = v; m0 = fmaxf(m0, v);
        v = (s + 1 <= t0) ? fmaf(scale, sa[nt][1], __high2float(q0)) : -INFINITY;
        sa[nt][1] = v; m0 = fmaxf(m0, v);
        v = (s     <= t1) ? fmaf(scale, sa[nt][2], __low2float(q1))  : -INFINITY;
        sa[nt][2] = v; m1 = fmaxf(m1, v);
        v = (s + 1 <= t1) ? fmaf(scale, sa[nt][3], __high2float(q1)) : -INFINITY;
        sa[nt][3] = v; m1 = fmaxf(m1, v);
    }
    m0 = fmaxf(m0, __shfl_xor_sync(0xffffffffu, m0, 1));
    m0 = fmaxf(m0, __shfl_xor_sync(0xffffffffu, m0, 2));
    m1 = fmaxf(m1, __shfl_xor_sync(0xffffffffu, m1, 1));
    m1 = fmaxf(m1, __shfl_xor_sync(0xffffffffu, m1, 2));
    float l0 = 0.f, l1 = 0.f;
#pragma unroll
    for (int nt = 0; nt < 16; nt++) {
        sa[nt][0] = __expf(sa[nt][0] - m0); l0 += sa[nt][0];
        sa[nt][1] = __expf(sa[nt][1] - m0); l0 += sa[nt][1];
        sa[nt][2] = __expf(sa[nt][2] - m1); l1 += sa[nt][2];
        sa[nt][3] = __expf(sa[nt][3] - m1); l1 += sa[nt][3];
    }
    l0 += __shfl_xor_sync(0xffffffffu, l0, 1);
    l0 += __shfl_xor_sync(0xffffffffu, l0, 2);
    l1 += __shfl_xor_sync(0xffffffffu, l1, 1);
    l1 += __shfl_xor_sync(0xffffffffu, l1, 2);
    const float inv0 = 1.f / l0, inv1 = 1.f / l1;

    // O GEMM
    float oa[3][4];
#pragma unroll
    for (int nt = 0; nt < 3; nt++)
#pragma unroll
        for (int i = 0; i < 4; i++) oa[nt][i] = 0.f;
    const uint32_t vrow = (uint32_t)(((lane & 7) + ((lane >> 3) & 1) * 8) * 80);
    const uint32_t vt4 = vrow + ((lane >> 4) & 1) * 16;
    const uint32_t vt2 = vrow + 32;
#pragma unroll
    for (int i = 0; i < 8; i++) {
        uint32_t ah[4], al[4];
        bsplit(sa[2 * i][0],     sa[2 * i][1],     ah[0], al[0]);
        bsplit(sa[2 * i][2],     sa[2 * i][3],     ah[1], al[1]);
        bsplit(sa[2 * i + 1][0], sa[2 * i + 1][1], ah[2], al[2]);
        bsplit(sa[2 * i + 1][2], sa[2 * i + 1][3], ah[3], al[3]);
        uint32_t bh0, bh1, bh2, bh3, bh4, bh5;
        uint32_t bl0, bl1, bl2, bl3, bl4, bl5;
        LDSM4T(bh0, bh1, bh2, bh3, su + AVH + i * 1280 + vt4);
        LDSM2T(bh4, bh5,           su + AVH + i * 1280 + vt2);
        LDSM4T(bl0, bl1, bl2, bl3, su + AVL + i * 1280 + vt4);
        LDSM2T(bl4, bl5,           su + AVL + i * 1280 + vt2);
        MMA16816(oa[0], ah[0], ah[1], ah[2], ah[3], bh0, bh1);
        MMA16816(oa[0], al[0], al[1], al[2], al[3], bh0, bh1);
        MMA16816(oa[0], ah[0], ah[1], ah[2], ah[3], bl0, bl1);
        MMA16816(oa[1], ah[0], ah[1], ah[2], ah[3], bh2, bh3);
        MMA16816(oa[1], al[0], al[1], al[2], al[3], bh2, bh3);
        MMA16816(oa[1], ah[0], ah[1], ah[2], ah[3], bl2, bl3);
        MMA16816(oa[2], ah[0], ah[1], ah[2], ah[3], bh4, bh5);
        MMA16816(oa[2], al[0], al[1], al[2], al[3], bh4, bh5);
        MMA16816(oa[2], ah[0], ah[1], ah[2], ah[3], bl4, bl5);
    }

    // epilogue: ctx -> bf16 hi/lo images for proj
    const size_t ro0 = (size_t)b * (TT * NE) + (size_t)t0 * NE + h * HS;
    const size_t ro1 = (size_t)b * (TT * NE) + (size_t)t1 * NE + h * HS;
#pragma unroll
    for (int nt = 0; nt < 3; nt++) {
        int d = nt * 8 + tg * 2;
        uint32_t hh, ll;
        bsplit(oa[nt][0] * inv0, oa[nt][1] * inv0, hh, ll);
        *(uint32_t*)(g_ctxh + ro0 + d) = hh;
        *(uint32_t*)(g_ctxl + ro0 + d) = ll;
        bsplit(oa[nt][2] * inv1, oa[nt][3] * inv1, hh, ll);
        *(uint32_t*)(g_ctxh + ro1 + d) = hh;
        *(uint32_t*)(g_ctxl + ro1 + d) = ll;
    }
}

// ---------------------------------------------------------------------------
// kernel_launch
// Inputs: 0=x, 1=Wq, 2=Wk, 3=Wv, 4=rel_table, 5=Wproj, 6=bproj (all fp32)
// ---------------------------------------------------------------------------
extern "C" void kernel_launch(void* const* d_in, const int* in_sizes, int n_in,
                              void* d_out, int out_size) {
    const float* x   = (const float*)d_in[0];
    const float* Wq  = (const float*)d_in[1];
    const float* Wk  = (const float*)d_in[2];
    const float* Wv  = (const float*)d_in[3];
    const float* rel = (const float*)d_in[4];
    const float* Wp  = (const float*)d_in[5];
    const float* bp  = (const float*)d_in[6];
    float* out = (float*)d_out;

    const int M = in_sizes[0] / NE;   // 32768
    const int B = M / TT;             // 256

    (void)cudaFuncSetAttribute(gemm_qkv_mma,
                               cudaFuncAttributeMaxDynamicSharedMemorySize, GEMM_SMEM);
    (void)cudaFuncSetAttribute(gemm_proj_mma,
                               cudaFuncAttributeMaxDynamicSharedMemorySize, GEMM_SMEM);
    (void)cudaFuncSetAttribute(attn_kernel,
                               cudaFuncAttributeMaxDynamicSharedMemorySize, ATTN_SMEM);

    prep_w<<<4, 256>>>(Wq, Wk, Wv, Wp);
    prep_a<<<(M * NE / 4) / 256, 256>>>(x);
    prep_rel<<<1, 256>>>(rel);

    gemm_qkv_mma<<<dim3(M / 64, 3), 256, GEMM_SMEM>>>();

    attn_kernel<<<dim3(NHEADS, B), 256, ATTN_SMEM>>>();

    gemm_proj_mma<<<dim3(M / 64, 1), 256, GEMM_SMEM>>>(bp, out);
}